// round 6
// baseline (speedup 1.0000x reference)
#include <cuda_runtime.h>
#include <cuda_bf16.h>
#include <math.h>

#define MAXN 50048
#define MAXE 800256

// ---------------- scratch (static device globals; no allocs) ----------------
__device__ float g_bufA[MAXN * 192];
__device__ float g_bufB[MAXN * 192];
__device__ float g_as[MAXN * 3];
__device__ float g_ad[MAXN * 3];
__device__ int   g_deg[MAXN];
__device__ int   g_cnt[MAXN];
__device__ int   g_offs[MAXN + 1];
__device__ int   g_csr[MAXE];
__device__ int   g_src[MAXE];
__device__ int   g_dst[MAXE];
__device__ int   g_is64;

// ---------------- edge dtype detection + normalization ----------------
// If the buffer is really int64 (little-endian, non-negative values < N),
// every odd int32 position is 0. If it's int32, odd positions are genuine
// indices and the chance all sampled ones are zero is ~0.
__global__ void detect_kernel(const unsigned int* __restrict__ p, int E) {
    __shared__ int any;
    if (threadIdx.x == 0) any = 0;
    __syncthreads();
    int nsamp = min(E, 4096);
    for (int i = threadIdx.x; i < nsamp; i += 256)
        if (p[2 * i + 1] != 0u) any = 1;
    __syncthreads();
    if (threadIdx.x == 0) g_is64 = (any == 0) ? 1 : 0;
}

__global__ void conv_edges(const void* __restrict__ ei, int E, int Nn) {
    int i = blockIdx.x * blockDim.x + threadIdx.x;
    if (i >= E) return;
    int s, d;
    if (g_is64) {
        const long long* p = (const long long*)ei;
        s = (int)p[i];
        d = (int)p[(size_t)E + i];
    } else {
        const int* p = (const int*)ei;
        s = p[i];
        d = p[E + i];
    }
    // hard clamp: no downstream index can ever go out of bounds
    s = min(max(s, 0), Nn - 1);
    d = min(max(d, 0), Nn - 1);
    g_src[i] = s;
    g_dst[i] = d;
}

// ---------------- CSR build ----------------
__global__ void zero_kernel(int n) {
    int i = blockIdx.x * blockDim.x + threadIdx.x;
    if (i < n) { g_deg[i] = 0; g_cnt[i] = 0; }
}

__global__ void deg_kernel(int E) {
    int i = blockIdx.x * blockDim.x + threadIdx.x;
    if (i < E) atomicAdd(&g_deg[g_dst[i]], 1);
}

__global__ void scan_kernel(int n) {
    __shared__ int sm[1024];
    __shared__ int carry;
    int tid = threadIdx.x;
    if (tid == 0) { carry = 0; g_offs[0] = 0; }
    __syncthreads();
    for (int base = 0; base < n; base += 1024) {
        int i = base + tid;
        int v = (i < n) ? g_deg[i] : 0;
        sm[tid] = v;
        __syncthreads();
        for (int d = 1; d < 1024; d <<= 1) {
            int t = (tid >= d) ? sm[tid - d] : 0;
            __syncthreads();
            sm[tid] += t;
            __syncthreads();
        }
        int incl = sm[tid] + carry;
        if (i < n) g_offs[i + 1] = incl;
        __syncthreads();
        if (tid == 1023) carry = incl;
        __syncthreads();
    }
}

__global__ void scat_kernel(int E) {
    int i = blockIdx.x * blockDim.x + threadIdx.x;
    if (i < E) {
        int d = g_dst[i];
        int pos = g_offs[d] + atomicAdd(&g_cnt[d], 1);
        g_csr[pos] = g_src[i];
    }
}

// ---------------- SGEMM: Y[M,OUT] = X[M,K] @ W[K,OUT] (+ epilogue) ----------------
// epi: 0 = none; 1 = + bias_a + bias_b + extra (skip path); 2 = elu(+ bias_a) (lin1)
template <int OUT>
__global__ void __launch_bounds__(256) gemm_kernel(
    const float* __restrict__ X, const float* __restrict__ W, float* __restrict__ Y,
    int M, int K, int epi,
    const float* __restrict__ bias_a, const float* __restrict__ bias_b,
    const float* __restrict__ extra)
{
    constexpr int TN = OUT / 16;
    __shared__ float xs[64][33];
    __shared__ float ws[32][OUT];
    int tid = threadIdx.x;
    int tx = tid & 15, ty = tid >> 4;
    int row0 = blockIdx.x * 64;

    float acc[4][TN];
#pragma unroll
    for (int i = 0; i < 4; i++)
#pragma unroll
        for (int j = 0; j < TN; j++) acc[i][j] = 0.f;

    for (int k0 = 0; k0 < K; k0 += 32) {
#pragma unroll
        for (int idx = tid; idx < 64 * 32; idx += 256) {
            int r = idx >> 5, kk = idx & 31;
            int gr = row0 + r;
            xs[r][kk] = (gr < M) ? X[(size_t)gr * K + k0 + kk] : 0.f;
        }
#pragma unroll
        for (int idx = tid; idx < 32 * OUT; idx += 256) {
            int kk = idx / OUT, c = idx % OUT;
            ws[kk][c] = W[(size_t)(k0 + kk) * OUT + c];
        }
        __syncthreads();
#pragma unroll 4
        for (int kk = 0; kk < 32; kk++) {
            float a0 = xs[ty * 4 + 0][kk];
            float a1 = xs[ty * 4 + 1][kk];
            float a2 = xs[ty * 4 + 2][kk];
            float a3 = xs[ty * 4 + 3][kk];
            float b[TN];
#pragma unroll
            for (int j = 0; j < TN; j++) b[j] = ws[kk][tx + 16 * j];
#pragma unroll
            for (int j = 0; j < TN; j++) {
                acc[0][j] += a0 * b[j];
                acc[1][j] += a1 * b[j];
                acc[2][j] += a2 * b[j];
                acc[3][j] += a3 * b[j];
            }
        }
        __syncthreads();
    }

#pragma unroll
    for (int i = 0; i < 4; i++) {
        int gr = row0 + ty * 4 + i;
        if (gr < M) {
#pragma unroll
            for (int j = 0; j < TN; j++) {
                int c = tx + 16 * j;
                float v = acc[i][j];
                if (epi == 1) {
                    v += bias_a[c] + bias_b[c] + extra[(size_t)gr * OUT + c];
                } else if (epi == 2) {
                    v += bias_a[c];
                    v = (v > 0.f) ? v : (expm1f(v));
                }
                Y[(size_t)gr * OUT + c] = v;
            }
        }
    }
}

// ---------------- alpha_src / alpha_dst: [N,H] dot products ----------------
template <int H>
__global__ void alpha_kernel(const float* __restrict__ hpre,
                             const float* __restrict__ a_src, const float* __restrict__ a_dst,
                             int Nn)
{
    int warp = (blockIdx.x * blockDim.x + threadIdx.x) >> 5;
    int lane = threadIdx.x & 31;
    if (warp >= Nn) return;
    const float* hrow = hpre + (size_t)warp * (H * 64);
#pragma unroll
    for (int h = 0; h < H; h++) {
        float h0 = hrow[h * 64 + lane];
        float h1 = hrow[h * 64 + 32 + lane];
        float s = h0 * a_src[h * 64 + lane] + h1 * a_src[h * 64 + 32 + lane];
        float d = h0 * a_dst[h * 64 + lane] + h1 * a_dst[h * 64 + 32 + lane];
#pragma unroll
        for (int o = 16; o >= 1; o >>= 1) {
            s += __shfl_xor_sync(0xffffffffu, s, o);
            d += __shfl_xor_sync(0xffffffffu, d, o);
        }
        if (lane == 0) { g_as[warp * H + h] = s; g_ad[warp * H + h] = d; }
    }
}

// ---------------- softmax-aggregation: one warp per dst node (atomic-free) ----------------
// mode 0: out = elu(BN(acc + bias)); mode 1: out = acc (raw, layer 3)
template <int H>
__global__ void __launch_bounds__(256) agg_kernel(
    const float* __restrict__ hpre,
    const float* __restrict__ bias,
    const float* __restrict__ bng, const float* __restrict__ bnb,
    const float* __restrict__ bnm, const float* __restrict__ bnv,
    float* __restrict__ out, int Nn, int mode)
{
    int warp = (blockIdx.x * 256 + threadIdx.x) >> 5;
    int lane = threadIdx.x & 31;
    if (warp >= Nn) return;
    int start = g_offs[warp], end = g_offs[warp + 1];

    float adn[H], m[H], s[H];
#pragma unroll
    for (int h = 0; h < H; h++) { adn[h] = g_ad[warp * H + h]; m[h] = -1e30f; s[h] = 0.f; }

    // phase 1: online softmax stats, lanes strided over edges
    for (int i = start + lane; i < end; i += 32) {
        int src = g_csr[i];
#pragma unroll
        for (int h = 0; h < H; h++) {
            float e = g_as[src * H + h] + adn[h];
            e = (e > 0.f) ? e : 0.2f * e;
            if (e <= m[h]) {
                s[h] += __expf(e - m[h]);
            } else {
                s[h] = s[h] * __expf(m[h] - e) + 1.f;
                m[h] = e;
            }
        }
    }
#pragma unroll
    for (int o = 16; o >= 1; o >>= 1) {
#pragma unroll
        for (int h = 0; h < H; h++) {
            float om = __shfl_xor_sync(0xffffffffu, m[h], o);
            float os = __shfl_xor_sync(0xffffffffu, s[h], o);
            float nm = fmaxf(m[h], om);
            s[h] = s[h] * __expf(m[h] - nm) + os * __expf(om - nm);
            m[h] = nm;
        }
    }
    float invd[H];
#pragma unroll
    for (int h = 0; h < H; h++) invd[h] = 1.f / (s[h] + 1e-16f);

    // phase 2: weighted aggregation. Weights computed once per edge
    // (lane-parallel over a batch of 32 edges), broadcast via shfl;
    // row loads are whole-warp coalesced.
    float acc[H][2];
#pragma unroll
    for (int h = 0; h < H; h++) { acc[h][0] = 0.f; acc[h][1] = 0.f; }

    for (int base = start; base < end; base += 32) {
        int nb = min(32, end - base);
        int src_l = 0;
        float w_l[H];
#pragma unroll
        for (int h = 0; h < H; h++) w_l[h] = 0.f;
        if (base + lane < end) {
            src_l = g_csr[base + lane];
#pragma unroll
            for (int h = 0; h < H; h++) {
                float e = g_as[src_l * H + h] + adn[h];
                e = (e > 0.f) ? e : 0.2f * e;
                w_l[h] = __expf(e - m[h]) * invd[h];
            }
        }
        for (int j = 0; j < nb; j++) {
            int src = __shfl_sync(0xffffffffu, src_l, j);
            const float* hr = hpre + (size_t)src * (H * 64);
#pragma unroll
            for (int h = 0; h < H; h++) {
                float w = __shfl_sync(0xffffffffu, w_l[h], j);
                acc[h][0] += w * hr[h * 64 + lane];
                acc[h][1] += w * hr[h * 64 + 32 + lane];
            }
        }
    }

    float* orow = out + (size_t)warp * (H * 64);
#pragma unroll
    for (int h = 0; h < H; h++) {
#pragma unroll
        for (int p = 0; p < 2; p++) {
            int c = h * 64 + p * 32 + lane;
            float v = acc[h][p];
            if (mode == 0) {
                v += bias[c];
                v = (v - bnm[c]) * (bng[c] * rsqrtf(bnv[c] + 1e-5f)) + bnb[c];
                v = (v > 0.f) ? v : expm1f(v);
            }
            orow[c] = v;
        }
    }
}

// ---------------- head: logits = u @ W2[64,8] + b, then log_softmax ----------------
__global__ void head_kernel(const float* __restrict__ u, const float* __restrict__ W,
                            const float* __restrict__ b, float* __restrict__ out, int Nn)
{
    int gtid = blockIdx.x * blockDim.x + threadIdx.x;
    int lane = threadIdx.x & 31;
    int warpg = gtid >> 5;
    int sub = lane >> 3, cls = lane & 7;
    int node = warpg * 4 + sub;
    float acc = 0.f;
    if (node < Nn) {
        const float* ur = u + (size_t)node * 64;
#pragma unroll 8
        for (int k = 0; k < 64; k++) acc += ur[k] * W[k * 8 + cls];
        acc += b[cls];
    }
    float mx = acc;
#pragma unroll
    for (int o = 4; o >= 1; o >>= 1) mx = fmaxf(mx, __shfl_xor_sync(0xffffffffu, mx, o));
    float se = expf(acc - mx);
#pragma unroll
    for (int o = 4; o >= 1; o >>= 1) se += __shfl_xor_sync(0xffffffffu, se, o);
    if (node < Nn) out[(size_t)node * 8 + cls] = acc - mx - logf(se);
}

// ---------------- host orchestration ----------------
extern "C" void kernel_launch(void* const* d_in, const int* in_sizes, int n_in,
                              void* d_out, int out_size)
{
    const float* x     = (const float*)d_in[0];
    const void*  ei    = d_in[1];
    const float* W1    = (const float*)d_in[2];
    const float* asr1  = (const float*)d_in[3];
    const float* adt1  = (const float*)d_in[4];
    const float* b1    = (const float*)d_in[5];
    const float* bn1g  = (const float*)d_in[6];
    const float* bn1b  = (const float*)d_in[7];
    const float* bn1m  = (const float*)d_in[8];
    const float* bn1v  = (const float*)d_in[9];
    const float* W2    = (const float*)d_in[10];
    const float* asr2  = (const float*)d_in[11];
    const float* adt2  = (const float*)d_in[12];
    const float* b2    = (const float*)d_in[13];
    const float* bn2g  = (const float*)d_in[14];
    const float* bn2b  = (const float*)d_in[15];
    const float* bn2m  = (const float*)d_in[16];
    const float* bn2v  = (const float*)d_in[17];
    const float* W3    = (const float*)d_in[18];
    const float* asr3  = (const float*)d_in[19];
    const float* adt3  = (const float*)d_in[20];
    const float* b3    = (const float*)d_in[21];
    const float* skipW = (const float*)d_in[22];
    const float* skipb = (const float*)d_in[23];
    const float* l1W   = (const float*)d_in[24];
    const float* l1b   = (const float*)d_in[25];
    const float* l2W   = (const float*)d_in[26];
    const float* l2b   = (const float*)d_in[27];

    int Nn = in_sizes[0] / 64;
    int E  = in_sizes[1] / 2;
    if (Nn > MAXN) Nn = MAXN;
    if (E > MAXE) E = MAXE;

    float *bufA, *bufB;
    cudaGetSymbolAddress((void**)&bufA, g_bufA);
    cudaGetSymbolAddress((void**)&bufB, g_bufB);

    int eb = (E + 255) / 256;
    int nb = (Nn + 1 + 255) / 256;

    // --- edge dtype normalization + CSR build ---
    detect_kernel<<<1, 256>>>((const unsigned int*)ei, E);
    conv_edges<<<eb, 256>>>(ei, E, Nn);
    zero_kernel<<<nb, 256>>>(Nn);
    deg_kernel<<<eb, 256>>>(E);
    scan_kernel<<<1, 1024>>>(Nn);
    scat_kernel<<<eb, 256>>>(E);

    int gb = (Nn + 63) / 64;
    int wb = (Nn * 32 + 255) / 256;   // one warp per node
    int ab = (Nn + 7) / 8;            // 8 warps per block

    // --- layer 1: 64 -> 3x64 ---
    gemm_kernel<192><<<gb, 256>>>(x, W1, bufA, Nn, 64, 0, nullptr, nullptr, nullptr);
    alpha_kernel<3><<<wb, 256>>>(bufA, asr1, adt1, Nn);
    agg_kernel<3><<<ab, 256>>>(bufA, b1, bn1g, bn1b, bn1m, bn1v, bufB, Nn, 0);

    // --- layer 2: 192 -> 2x64 ---
    gemm_kernel<128><<<gb, 256>>>(bufB, W2, bufA, Nn, 192, 0, nullptr, nullptr, nullptr);
    alpha_kernel<2><<<wb, 256>>>(bufA, asr2, adt2, Nn);
    agg_kernel<2><<<ab, 256>>>(bufA, b2, bn2g, bn2b, bn2m, bn2v, bufB, Nn, 0);

    // --- layer 3: 128 -> 64 (raw aggregation; b3 folded into skip epilogue) ---
    gemm_kernel<64><<<gb, 256>>>(bufB, W3, bufA, Nn, 128, 0, nullptr, nullptr, nullptr);
    alpha_kernel<1><<<wb, 256>>>(bufA, asr3, adt3, Nn);
    agg_kernel<1><<<ab, 256>>>(bufA, nullptr, nullptr, nullptr, nullptr, nullptr, bufB, Nn, 1);

    // --- skip: t = x@skipW + skip_b + b3 + agg3 ---
    gemm_kernel<64><<<gb, 256>>>(x, skipW, bufA, Nn, 64, 1, skipb, b3, bufB);
    // --- lin1: u = elu(t@l1W + l1b) ---
    gemm_kernel<64><<<gb, 256>>>(bufA, l1W, bufB, Nn, 64, 2, l1b, nullptr, nullptr);
    // --- lin2 + log_softmax ---
    head_kernel<<<(Nn * 8 + 255) / 256, 256>>>(bufB, l2W, l2b, (float*)d_out, Nn);
}

// round 7
// speedup vs baseline: 1.1535x; 1.1535x over previous
#include <cuda_runtime.h>
#include <cuda_bf16.h>
#include <math.h>

#define MAXN 50048
#define MAXE 800256

// ---------------- scratch (static device globals; no allocs) ----------------
__device__ float g_bufA[MAXN * 192];
__device__ float g_bufB[MAXN * 192];
__device__ float g_as[MAXN * 3];
__device__ float g_ad[MAXN * 3];
__device__ int   g_deg[MAXN];
__device__ int   g_cnt[MAXN];
__device__ int   g_offs[MAXN + 1];
__device__ int   g_csr[MAXE];
__device__ int   g_src[MAXE];
__device__ int   g_dst[MAXE];
__device__ int   g_bsum[64];
__device__ int   g_btop[64];
__device__ int   g_is64;

// ---------------- edge dtype detection + normalization ----------------
__global__ void detect_kernel(const unsigned int* __restrict__ p, int E) {
    __shared__ int any;
    if (threadIdx.x == 0) any = 0;
    __syncthreads();
    int nsamp = min(E, 4096);
    for (int i = threadIdx.x; i < nsamp; i += 256)
        if (p[2 * i + 1] != 0u) any = 1;
    __syncthreads();
    if (threadIdx.x == 0) g_is64 = (any == 0) ? 1 : 0;
}

__global__ void zero_kernel(int n) {
    int i = blockIdx.x * blockDim.x + threadIdx.x;
    if (i < n) { g_deg[i] = 0; g_cnt[i] = 0; }
}

// convert + clamp + degree histogram in one pass
__global__ void conv_deg_kernel(const void* __restrict__ ei, int E, int Nn) {
    int i = blockIdx.x * blockDim.x + threadIdx.x;
    if (i >= E) return;
    int s, d;
    if (g_is64) {
        const long long* p = (const long long*)ei;
        s = (int)p[i];
        d = (int)p[(size_t)E + i];
    } else {
        const int* p = (const int*)ei;
        s = p[i];
        d = p[E + i];
    }
    s = min(max(s, 0), Nn - 1);
    d = min(max(d, 0), Nn - 1);
    g_src[i] = s;
    g_dst[i] = d;
    atomicAdd(&g_deg[d], 1);
}

// ---------------- hierarchical scan: offs = exclusive-prefix(deg) ----------------
__global__ void scan_blocks(int n) {
    __shared__ int sm[1024];
    int tid = threadIdx.x;
    int i = blockIdx.x * 1024 + tid;
    int v = (i < n) ? g_deg[i] : 0;
    sm[tid] = v;
    __syncthreads();
#pragma unroll
    for (int d = 1; d < 1024; d <<= 1) {
        int t = (tid >= d) ? sm[tid - d] : 0;
        __syncthreads();
        sm[tid] += t;
        __syncthreads();
    }
    if (i < n) g_offs[i + 1] = sm[tid];
    if (tid == 1023) g_bsum[blockIdx.x] = sm[1023];
}

__global__ void scan_tops(int nb) {
    __shared__ int sm[64];
    int tid = threadIdx.x;
    sm[tid] = (tid < nb) ? g_bsum[tid] : 0;
    __syncthreads();
#pragma unroll
    for (int d = 1; d < 64; d <<= 1) {
        int t = (tid >= d) ? sm[tid - d] : 0;
        __syncthreads();
        sm[tid] += t;
        __syncthreads();
    }
    // exclusive prefix for block-add step
    g_btop[tid] = (tid == 0) ? 0 : sm[tid - 1];
}

__global__ void scan_add(int n) {
    int i = blockIdx.x * 1024 + threadIdx.x;
    if (i < n) g_offs[i + 1] += g_btop[blockIdx.x];
    if (i == 0) g_offs[0] = 0;
}

__global__ void scat_kernel(int E) {
    int i = blockIdx.x * blockDim.x + threadIdx.x;
    if (i < E) {
        int d = g_dst[i];
        int pos = g_offs[d] + atomicAdd(&g_cnt[d], 1);
        g_csr[pos] = g_src[i];
    }
}

// ---------------- SGEMM: Y[M,OUT] = X[M,K] @ W[K,OUT] (+ epilogue) ----------------
// epi: 0 = none; 1 = + bias_a + bias_b + extra (skip path); 2 = elu(+ bias_a) (lin1)
template <int OUT>
__global__ void __launch_bounds__(256) gemm_kernel(
    const float* __restrict__ X, const float* __restrict__ W, float* __restrict__ Y,
    int M, int K, int epi,
    const float* __restrict__ bias_a, const float* __restrict__ bias_b,
    const float* __restrict__ extra)
{
    constexpr int TN = OUT / 16;
    __shared__ float xs[64][33];
    __shared__ float ws[32][OUT];
    int tid = threadIdx.x;
    int tx = tid & 15, ty = tid >> 4;
    int row0 = blockIdx.x * 64;

    float acc[4][TN];
#pragma unroll
    for (int i = 0; i < 4; i++)
#pragma unroll
        for (int j = 0; j < TN; j++) acc[i][j] = 0.f;

    for (int k0 = 0; k0 < K; k0 += 32) {
#pragma unroll
        for (int idx = tid; idx < 64 * 32; idx += 256) {
            int r = idx >> 5, kk = idx & 31;
            int gr = row0 + r;
            xs[r][kk] = (gr < M) ? X[(size_t)gr * K + k0 + kk] : 0.f;
        }
#pragma unroll
        for (int idx = tid; idx < 32 * OUT; idx += 256) {
            int kk = idx / OUT, c = idx % OUT;
            ws[kk][c] = W[(size_t)(k0 + kk) * OUT + c];
        }
        __syncthreads();
#pragma unroll 4
        for (int kk = 0; kk < 32; kk++) {
            float a0 = xs[ty * 4 + 0][kk];
            float a1 = xs[ty * 4 + 1][kk];
            float a2 = xs[ty * 4 + 2][kk];
            float a3 = xs[ty * 4 + 3][kk];
            float b[TN];
#pragma unroll
            for (int j = 0; j < TN; j++) b[j] = ws[kk][tx + 16 * j];
#pragma unroll
            for (int j = 0; j < TN; j++) {
                acc[0][j] += a0 * b[j];
                acc[1][j] += a1 * b[j];
                acc[2][j] += a2 * b[j];
                acc[3][j] += a3 * b[j];
            }
        }
        __syncthreads();
    }

#pragma unroll
    for (int i = 0; i < 4; i++) {
        int gr = row0 + ty * 4 + i;
        if (gr < M) {
#pragma unroll
            for (int j = 0; j < TN; j++) {
                int c = tx + 16 * j;
                float v = acc[i][j];
                if (epi == 1) {
                    v += bias_a[c] + bias_b[c] + extra[(size_t)gr * OUT + c];
                } else if (epi == 2) {
                    v += bias_a[c];
                    v = (v > 0.f) ? v : (expm1f(v));
                }
                Y[(size_t)gr * OUT + c] = v;
            }
        }
    }
}

// ---------------- alpha_src / alpha_dst: [N,H] dot products ----------------
template <int H>
__global__ void alpha_kernel(const float* __restrict__ hpre,
                             const float* __restrict__ a_src, const float* __restrict__ a_dst,
                             int Nn)
{
    int warp = (blockIdx.x * blockDim.x + threadIdx.x) >> 5;
    int lane = threadIdx.x & 31;
    if (warp >= Nn) return;
    const float* hrow = hpre + (size_t)warp * (H * 64);
#pragma unroll
    for (int h = 0; h < H; h++) {
        float h0 = hrow[h * 64 + lane];
        float h1 = hrow[h * 64 + 32 + lane];
        float s = h0 * a_src[h * 64 + lane] + h1 * a_src[h * 64 + 32 + lane];
        float d = h0 * a_dst[h * 64 + lane] + h1 * a_dst[h * 64 + 32 + lane];
#pragma unroll
        for (int o = 16; o >= 1; o >>= 1) {
            s += __shfl_xor_sync(0xffffffffu, s, o);
            d += __shfl_xor_sync(0xffffffffu, d, o);
        }
        if (lane == 0) { g_as[warp * H + h] = s; g_ad[warp * H + h] = d; }
    }
}

// ---------------- softmax-aggregation: one warp per dst node (atomic-free) ----------------
// Pass 1: max of as[src] per head (leaky_relu is monotone, adn constant per dst,
// so max_e = lrelu(max_as + adn)). Pass 2: unnormalized exp weights, fused
// denominator sum + weighted accumulation; single normalize at the end.
// mode 0: out = elu(BN(acc + bias)); mode 1: out = acc (raw, layer 3)
template <int H>
__global__ void __launch_bounds__(256) agg_kernel(
    const float* __restrict__ hpre,
    const float* __restrict__ bias,
    const float* __restrict__ bng, const float* __restrict__ bnb,
    const float* __restrict__ bnm, const float* __restrict__ bnv,
    float* __restrict__ out, int Nn, int mode)
{
    int warp = (blockIdx.x * 256 + threadIdx.x) >> 5;
    int lane = threadIdx.x & 31;
    if (warp >= Nn) return;
    int start = g_offs[warp], end = g_offs[warp + 1];

    float adn[H];
#pragma unroll
    for (int h = 0; h < H; h++) adn[h] = g_ad[warp * H + h];

    // pass 1: max of alpha_src over incoming edges (no exp, no branches)
    float ma[H];
#pragma unroll
    for (int h = 0; h < H; h++) ma[h] = -1e30f;
    for (int i = start + lane; i < end; i += 32) {
        int src = g_csr[i];
#pragma unroll
        for (int h = 0; h < H; h++) ma[h] = fmaxf(ma[h], g_as[src * H + h]);
    }
#pragma unroll
    for (int o = 16; o >= 1; o >>= 1)
#pragma unroll
        for (int h = 0; h < H; h++)
            ma[h] = fmaxf(ma[h], __shfl_xor_sync(0xffffffffu, ma[h], o));

    float m[H];
#pragma unroll
    for (int h = 0; h < H; h++) {
        float e = ma[h] + adn[h];
        m[h] = (e > 0.f) ? e : 0.2f * e;
    }

    // pass 2: fused exp-weight + denominator + weighted aggregation
    float acc[H][2], ssum[H];
#pragma unroll
    for (int h = 0; h < H; h++) { acc[h][0] = 0.f; acc[h][1] = 0.f; ssum[h] = 0.f; }

    for (int base = start; base < end; base += 32) {
        int nb = min(32, end - base);
        int src_l = 0;
        float w_l[H];
#pragma unroll
        for (int h = 0; h < H; h++) w_l[h] = 0.f;
        if (base + lane < end) {
            src_l = g_csr[base + lane];
#pragma unroll
            for (int h = 0; h < H; h++) {
                float e = g_as[src_l * H + h] + adn[h];
                e = (e > 0.f) ? e : 0.2f * e;
                float w = __expf(e - m[h]);
                w_l[h] = w;
                ssum[h] += w;
            }
        }
        for (int j = 0; j < nb; j++) {
            int src = __shfl_sync(0xffffffffu, src_l, j);
            const float* hr = hpre + (size_t)src * (H * 64);
#pragma unroll
            for (int h = 0; h < H; h++) {
                float w = __shfl_sync(0xffffffffu, w_l[h], j);
                acc[h][0] += w * hr[h * 64 + lane];
                acc[h][1] += w * hr[h * 64 + 32 + lane];
            }
        }
    }

    // warp-reduce denominators, then normalize once
#pragma unroll
    for (int o = 16; o >= 1; o >>= 1)
#pragma unroll
        for (int h = 0; h < H; h++)
            ssum[h] += __shfl_xor_sync(0xffffffffu, ssum[h], o);

    float inv[H];
#pragma unroll
    for (int h = 0; h < H; h++) inv[h] = 1.f / (ssum[h] + 1e-16f);

    float* orow = out + (size_t)warp * (H * 64);
#pragma unroll
    for (int h = 0; h < H; h++) {
#pragma unroll
        for (int p = 0; p < 2; p++) {
            int c = h * 64 + p * 32 + lane;
            float v = acc[h][p] * inv[h];
            if (mode == 0) {
                v += bias[c];
                v = (v - bnm[c]) * (bng[c] * rsqrtf(bnv[c] + 1e-5f)) + bnb[c];
                v = (v > 0.f) ? v : expm1f(v);
            }
            orow[c] = v;
        }
    }
}

// ---------------- head: logits = u @ W2[64,8] + b, then log_softmax ----------------
__global__ void head_kernel(const float* __restrict__ u, const float* __restrict__ W,
                            const float* __restrict__ b, float* __restrict__ out, int Nn)
{
    int gtid = blockIdx.x * blockDim.x + threadIdx.x;
    int lane = threadIdx.x & 31;
    int warpg = gtid >> 5;
    int sub = lane >> 3, cls = lane & 7;
    int node = warpg * 4 + sub;
    float acc = 0.f;
    if (node < Nn) {
        const float* ur = u + (size_t)node * 64;
#pragma unroll 8
        for (int k = 0; k < 64; k++) acc += ur[k] * W[k * 8 + cls];
        acc += b[cls];
    }
    float mx = acc;
#pragma unroll
    for (int o = 4; o >= 1; o >>= 1) mx = fmaxf(mx, __shfl_xor_sync(0xffffffffu, mx, o));
    float se = expf(acc - mx);
#pragma unroll
    for (int o = 4; o >= 1; o >>= 1) se += __shfl_xor_sync(0xffffffffu, se, o);
    if (node < Nn) out[(size_t)node * 8 + cls] = acc - mx - logf(se);
}

// ---------------- host orchestration ----------------
extern "C" void kernel_launch(void* const* d_in, const int* in_sizes, int n_in,
                              void* d_out, int out_size)
{
    const float* x     = (const float*)d_in[0];
    const void*  ei    = d_in[1];
    const float* W1    = (const float*)d_in[2];
    const float* asr1  = (const float*)d_in[3];
    const float* adt1  = (const float*)d_in[4];
    const float* b1    = (const float*)d_in[5];
    const float* bn1g  = (const float*)d_in[6];
    const float* bn1b  = (const float*)d_in[7];
    const float* bn1m  = (const float*)d_in[8];
    const float* bn1v  = (const float*)d_in[9];
    const float* W2    = (const float*)d_in[10];
    const float* asr2  = (const float*)d_in[11];
    const float* adt2  = (const float*)d_in[12];
    const float* b2    = (const float*)d_in[13];
    const float* bn2g  = (const float*)d_in[14];
    const float* bn2b  = (const float*)d_in[15];
    const float* bn2m  = (const float*)d_in[16];
    const float* bn2v  = (const float*)d_in[17];
    const float* W3    = (const float*)d_in[18];
    const float* asr3  = (const float*)d_in[19];
    const float* adt3  = (const float*)d_in[20];
    const float* b3    = (const float*)d_in[21];
    const float* skipW = (const float*)d_in[22];
    const float* skipb = (const float*)d_in[23];
    const float* l1W   = (const float*)d_in[24];
    const float* l1b   = (const float*)d_in[25];
    const float* l2W   = (const float*)d_in[26];
    const float* l2b   = (const float*)d_in[27];

    int Nn = in_sizes[0] / 64;
    int E  = in_sizes[1] / 2;
    if (Nn > MAXN) Nn = MAXN;
    if (E > MAXE) E = MAXE;

    float *bufA, *bufB;
    cudaGetSymbolAddress((void**)&bufA, g_bufA);
    cudaGetSymbolAddress((void**)&bufB, g_bufB);

    int eb = (E + 255) / 256;
    int nb = (Nn + 1 + 255) / 256;
    int sb = (Nn + 1023) / 1024;      // scan blocks (<= 49)

    // --- edge dtype normalization + CSR build ---
    detect_kernel<<<1, 256>>>((const unsigned int*)ei, E);
    zero_kernel<<<nb, 256>>>(Nn);
    conv_deg_kernel<<<eb, 256>>>(ei, E, Nn);
    scan_blocks<<<sb, 1024>>>(Nn);
    scan_tops<<<1, 64>>>(sb);
    scan_add<<<sb, 1024>>>(Nn);
    scat_kernel<<<eb, 256>>>(E);

    int gb = (Nn + 63) / 64;
    int wb = (Nn * 32 + 255) / 256;   // one warp per node
    int ab = (Nn + 7) / 8;            // 8 warps per block

    // --- layer 1: 64 -> 3x64 ---
    gemm_kernel<192><<<gb, 256>>>(x, W1, bufA, Nn, 64, 0, nullptr, nullptr, nullptr);
    alpha_kernel<3><<<wb, 256>>>(bufA, asr1, adt1, Nn);
    agg_kernel<3><<<ab, 256>>>(bufA, b1, bn1g, bn1b, bn1m, bn1v, bufB, Nn, 0);

    // --- layer 2: 192 -> 2x64 ---
    gemm_kernel<128><<<gb, 256>>>(bufB, W2, bufA, Nn, 192, 0, nullptr, nullptr, nullptr);
    alpha_kernel<2><<<wb, 256>>>(bufA, asr2, adt2, Nn);
    agg_kernel<2><<<ab, 256>>>(bufA, b2, bn2g, bn2b, bn2m, bn2v, bufB, Nn, 0);

    // --- layer 3: 128 -> 64 (raw aggregation; b3 folded into skip epilogue) ---
    gemm_kernel<64><<<gb, 256>>>(bufB, W3, bufA, Nn, 128, 0, nullptr, nullptr, nullptr);
    alpha_kernel<1><<<wb, 256>>>(bufA, asr3, adt3, Nn);
    agg_kernel<1><<<ab, 256>>>(bufA, nullptr, nullptr, nullptr, nullptr, nullptr, bufB, Nn, 1);

    // --- skip: t = x@skipW + skip_b + b3 + agg3 ---
    gemm_kernel<64><<<gb, 256>>>(x, skipW, bufA, Nn, 64, 1, skipb, b3, bufB);
    // --- lin1: u = elu(t@l1W + l1b) ---
    gemm_kernel<64><<<gb, 256>>>(bufA, l1W, bufB, Nn, 64, 2, l1b, nullptr, nullptr);
    // --- lin2 + log_softmax ---
    head_kernel<<<(Nn * 8 + 255) / 256, 256>>>(bufB, l2W, l2b, (float*)d_out, Nn);
}

// round 8
// speedup vs baseline: 1.3002x; 1.1272x over previous
#include <cuda_runtime.h>
#include <cuda_bf16.h>
#include <math.h>

#define MAXN 50048
#define MAXE 800256

// ---------------- scratch (static device globals; no allocs) ----------------
__device__ float g_bufA[MAXN * 192];
__device__ float g_bufB[MAXN * 192];
__device__ float g_as[MAXN * 3];
__device__ float g_ad[MAXN * 3];
__device__ int   g_deg[MAXN];
__device__ int   g_cnt[MAXN];
__device__ int   g_offs[MAXN + 1];
__device__ int   g_csr[MAXE];
__device__ int   g_src[MAXE];
__device__ int   g_dst[MAXE];
__device__ int   g_bsum[64];
__device__ int   g_btop[64];
__device__ int   g_is64;

// ---------------- packed f32x2 helpers ----------------
__device__ __forceinline__ unsigned long long pk2(float lo, float hi) {
    unsigned long long r;
    asm("mov.b64 %0, {%1, %2};" : "=l"(r) : "f"(lo), "f"(hi));
    return r;
}
__device__ __forceinline__ void upk2(float& lo, float& hi, unsigned long long v) {
    asm("mov.b64 {%0, %1}, %2;" : "=f"(lo), "=f"(hi) : "l"(v));
}
__device__ __forceinline__ unsigned long long fma2(unsigned long long a,
                                                   unsigned long long b,
                                                   unsigned long long c) {
    unsigned long long d;
    asm("fma.rn.f32x2 %0, %1, %2, %3;" : "=l"(d) : "l"(a), "l"(b), "l"(c));
    return d;
}

// ---------------- edge dtype detection + normalization ----------------
__global__ void detect_kernel(const unsigned int* __restrict__ p, int E) {
    __shared__ int any;
    if (threadIdx.x == 0) any = 0;
    __syncthreads();
    int nsamp = min(E, 4096);
    for (int i = threadIdx.x; i < nsamp; i += 256)
        if (p[2 * i + 1] != 0u) any = 1;
    __syncthreads();
    if (threadIdx.x == 0) g_is64 = (any == 0) ? 1 : 0;
}

__global__ void zero_kernel(int n) {
    int i = blockIdx.x * blockDim.x + threadIdx.x;
    if (i < n) { g_deg[i] = 0; g_cnt[i] = 0; }
}

// convert + clamp + degree histogram in one pass
__global__ void conv_deg_kernel(const void* __restrict__ ei, int E, int Nn) {
    int i = blockIdx.x * blockDim.x + threadIdx.x;
    if (i >= E) return;
    int s, d;
    if (g_is64) {
        const long long* p = (const long long*)ei;
        s = (int)p[i];
        d = (int)p[(size_t)E + i];
    } else {
        const int* p = (const int*)ei;
        s = p[i];
        d = p[E + i];
    }
    s = min(max(s, 0), Nn - 1);
    d = min(max(d, 0), Nn - 1);
    g_src[i] = s;
    g_dst[i] = d;
    atomicAdd(&g_deg[d], 1);
}

// ---------------- hierarchical scan: offs = exclusive-prefix(deg) ----------------
__global__ void scan_blocks(int n) {
    __shared__ int sm[1024];
    int tid = threadIdx.x;
    int i = blockIdx.x * 1024 + tid;
    int v = (i < n) ? g_deg[i] : 0;
    sm[tid] = v;
    __syncthreads();
#pragma unroll
    for (int d = 1; d < 1024; d <<= 1) {
        int t = (tid >= d) ? sm[tid - d] : 0;
        __syncthreads();
        sm[tid] += t;
        __syncthreads();
    }
    if (i < n) g_offs[i + 1] = sm[tid];
    if (tid == 1023) g_bsum[blockIdx.x] = sm[1023];
}

__global__ void scan_tops(int nb) {
    __shared__ int sm[64];
    int tid = threadIdx.x;
    sm[tid] = (tid < nb) ? g_bsum[tid] : 0;
    __syncthreads();
#pragma unroll
    for (int d = 1; d < 64; d <<= 1) {
        int t = (tid >= d) ? sm[tid - d] : 0;
        __syncthreads();
        sm[tid] += t;
        __syncthreads();
    }
    g_btop[tid] = (tid == 0) ? 0 : sm[tid - 1];
}

__global__ void scan_add(int n) {
    int i = blockIdx.x * 1024 + threadIdx.x;
    if (i < n) g_offs[i + 1] += g_btop[blockIdx.x];
    if (i == 0) g_offs[0] = 0;
}

__global__ void scat_kernel(int E) {
    int i = blockIdx.x * blockDim.x + threadIdx.x;
    if (i < E) {
        int d = g_dst[i];
        int pos = g_offs[d] + atomicAdd(&g_cnt[d], 1);
        g_csr[pos] = g_src[i];
    }
}

// ---------------- f32x2-packed SGEMM with fused alpha epilogue ----------------
// Y[M,OUT] = X[M,K] @ W[K,OUT] (+ epilogue). Requires K % 32 == 0.
// Column map: thread tx owns column pairs c = 2*tx + 32*jj, c+1.
// HEADS>0: also writes g_as/g_ad = per-head dot(h_row, a_src/a_dst).
// epi: 0 = none; 1 = + bias_a + bias_b + extra; 2 = elu(+ bias_a)
template <int OUT, int HEADS>
__global__ void __launch_bounds__(256) gemm_kernel(
    const float* __restrict__ X, const float* __restrict__ W, float* __restrict__ Y,
    int M, int K, int epi,
    const float* __restrict__ bias_a, const float* __restrict__ bias_b,
    const float* __restrict__ extra,
    const float* __restrict__ a_src, const float* __restrict__ a_dst)
{
    constexpr int TN2 = OUT / 32;
    constexpr int HM = (HEADS > 0) ? HEADS : 1;
    __shared__ __align__(16) float xsT[32][68];   // [k][row], row-padded to 68
    __shared__ __align__(16) float ws[32][OUT];
    __shared__ float sav[OUT], sdv[OUT];

    int tid = threadIdx.x;
    int tx = tid & 15, ty = tid >> 4;
    int row0 = blockIdx.x * 64;

    if (HEADS > 0) {
        for (int i = tid; i < OUT; i += 256) { sav[i] = a_src[i]; sdv[i] = a_dst[i]; }
    }

    unsigned long long acc2[4][TN2];
#pragma unroll
    for (int i = 0; i < 4; i++)
#pragma unroll
        for (int j = 0; j < TN2; j++) acc2[i][j] = 0ULL;

    for (int k0 = 0; k0 < K; k0 += 32) {
        // load X tile transposed: xsT[kk][r]
#pragma unroll
        for (int idx = tid; idx < 64 * 32; idx += 256) {
            int r = idx >> 5, kk = idx & 31;
            int gr = row0 + r;
            xsT[kk][r] = (gr < M) ? X[(size_t)gr * K + k0 + kk] : 0.f;
        }
#pragma unroll
        for (int idx = tid; idx < 32 * OUT; idx += 256) {
            int kk = idx / OUT, c = idx % OUT;
            ws[kk][c] = W[(size_t)(k0 + kk) * OUT + c];
        }
        __syncthreads();
#pragma unroll 8
        for (int kk = 0; kk < 32; kk++) {
            float4 av = *reinterpret_cast<const float4*>(&xsT[kk][ty * 4]);
            unsigned long long a0 = pk2(av.x, av.x);
            unsigned long long a1 = pk2(av.y, av.y);
            unsigned long long a2 = pk2(av.z, av.z);
            unsigned long long a3 = pk2(av.w, av.w);
#pragma unroll
            for (int jj = 0; jj < TN2; jj++) {
                unsigned long long bw = *reinterpret_cast<const unsigned long long*>(
                    &ws[kk][2 * tx + 32 * jj]);
                acc2[0][jj] = fma2(a0, bw, acc2[0][jj]);
                acc2[1][jj] = fma2(a1, bw, acc2[1][jj]);
                acc2[2][jj] = fma2(a2, bw, acc2[2][jj]);
                acc2[3][jj] = fma2(a3, bw, acc2[3][jj]);
            }
        }
        __syncthreads();
    }

    // epilogue: store + optional fused alpha dot products
#pragma unroll
    for (int i = 0; i < 4; i++) {
        int gr = row0 + ty * 4 + i;
        float asum[HM], dsum[HM];
#pragma unroll
        for (int h = 0; h < HM; h++) { asum[h] = 0.f; dsum[h] = 0.f; }
#pragma unroll
        for (int jj = 0; jj < TN2; jj++) {
            float lo, hi;
            upk2(lo, hi, acc2[i][jj]);
            int c0 = 2 * tx + 32 * jj;
            if (epi == 1) {
                if (gr < M) {
                    lo += bias_a[c0] + bias_b[c0] + extra[(size_t)gr * OUT + c0];
                    hi += bias_a[c0 + 1] + bias_b[c0 + 1] + extra[(size_t)gr * OUT + c0 + 1];
                }
            } else if (epi == 2) {
                lo += bias_a[c0];
                hi += bias_a[c0 + 1];
                lo = (lo > 0.f) ? lo : expm1f(lo);
                hi = (hi > 0.f) ? hi : expm1f(hi);
            }
            if (gr < M) {
                Y[(size_t)gr * OUT + c0] = lo;
                Y[(size_t)gr * OUT + c0 + 1] = hi;
            }
            if (HEADS > 0) {
                int h = jj >> 1;   // 64 cols per head, 32 per jj
                asum[h] += lo * sav[c0] + hi * sav[c0 + 1];
                dsum[h] += lo * sdv[c0] + hi * sdv[c0 + 1];
            }
        }
        if (HEADS > 0) {
#pragma unroll
            for (int h = 0; h < HM; h++) {
#pragma unroll
                for (int o = 8; o >= 1; o >>= 1) {
                    asum[h] += __shfl_xor_sync(0xffffffffu, asum[h], o);
                    dsum[h] += __shfl_xor_sync(0xffffffffu, dsum[h], o);
                }
            }
            if (tx == 0 && gr < M) {
#pragma unroll
                for (int h = 0; h < HM; h++) {
                    g_as[gr * HEADS + h] = asum[h];
                    g_ad[gr * HEADS + h] = dsum[h];
                }
            }
        }
    }
}

// ---------------- softmax-aggregation: one warp per dst node (atomic-free) ----------------
// Pass 1: max of as[src] per head. Pass 2: unnormalized exp weights, fused
// denominator + weighted accumulation; single normalize at the end.
// mode 0: out = elu(BN(acc + bias)); mode 1: out = acc (raw, layer 3)
template <int H>
__global__ void __launch_bounds__(256) agg_kernel(
    const float* __restrict__ hpre,
    const float* __restrict__ bias,
    const float* __restrict__ bng, const float* __restrict__ bnb,
    const float* __restrict__ bnm, const float* __restrict__ bnv,
    float* __restrict__ out, int Nn, int mode)
{
    int warp = (blockIdx.x * 256 + threadIdx.x) >> 5;
    int lane = threadIdx.x & 31;
    if (warp >= Nn) return;
    int start = g_offs[warp], end = g_offs[warp + 1];

    float adn[H];
#pragma unroll
    for (int h = 0; h < H; h++) adn[h] = g_ad[warp * H + h];

    float ma[H];
#pragma unroll
    for (int h = 0; h < H; h++) ma[h] = -1e30f;
    for (int i = start + lane; i < end; i += 32) {
        int src = g_csr[i];
#pragma unroll
        for (int h = 0; h < H; h++) ma[h] = fmaxf(ma[h], g_as[src * H + h]);
    }
#pragma unroll
    for (int o = 16; o >= 1; o >>= 1)
#pragma unroll
        for (int h = 0; h < H; h++)
            ma[h] = fmaxf(ma[h], __shfl_xor_sync(0xffffffffu, ma[h], o));

    float m[H];
#pragma unroll
    for (int h = 0; h < H; h++) {
        float e = ma[h] + adn[h];
        m[h] = (e > 0.f) ? e : 0.2f * e;
    }

    float acc[H][2], ssum[H];
#pragma unroll
    for (int h = 0; h < H; h++) { acc[h][0] = 0.f; acc[h][1] = 0.f; ssum[h] = 0.f; }

    for (int base = start; base < end; base += 32) {
        int nb = min(32, end - base);
        int src_l = 0;
        float w_l[H];
#pragma unroll
        for (int h = 0; h < H; h++) w_l[h] = 0.f;
        if (base + lane < end) {
            src_l = g_csr[base + lane];
#pragma unroll
            for (int h = 0; h < H; h++) {
                float e = g_as[src_l * H + h] + adn[h];
                e = (e > 0.f) ? e : 0.2f * e;
                float w = __expf(e - m[h]);
                w_l[h] = w;
                ssum[h] += w;
            }
        }
        for (int j = 0; j < nb; j++) {
            int src = __shfl_sync(0xffffffffu, src_l, j);
            const float* hr = hpre + (size_t)src * (H * 64);
#pragma unroll
            for (int h = 0; h < H; h++) {
                float w = __shfl_sync(0xffffffffu, w_l[h], j);
                acc[h][0] += w * hr[h * 64 + lane];
                acc[h][1] += w * hr[h * 64 + 32 + lane];
            }
        }
    }

#pragma unroll
    for (int o = 16; o >= 1; o >>= 1)
#pragma unroll
        for (int h = 0; h < H; h++)
            ssum[h] += __shfl_xor_sync(0xffffffffu, ssum[h], o);

    float inv[H];
#pragma unroll
    for (int h = 0; h < H; h++) inv[h] = 1.f / (ssum[h] + 1e-16f);

    float* orow = out + (size_t)warp * (H * 64);
#pragma unroll
    for (int h = 0; h < H; h++) {
#pragma unroll
        for (int p = 0; p < 2; p++) {
            int c = h * 64 + p * 32 + lane;
            float v = acc[h][p] * inv[h];
            if (mode == 0) {
                v += bias[c];
                v = (v - bnm[c]) * (bng[c] * rsqrtf(bnv[c] + 1e-5f)) + bnb[c];
                v = (v > 0.f) ? v : expm1f(v);
            }
            orow[c] = v;
        }
    }
}

// ---------------- head: logits = u @ W2[64,8] + b, then log_softmax ----------------
__global__ void head_kernel(const float* __restrict__ u, const float* __restrict__ W,
                            const float* __restrict__ b, float* __restrict__ out, int Nn)
{
    int gtid = blockIdx.x * blockDim.x + threadIdx.x;
    int lane = threadIdx.x & 31;
    int warpg = gtid >> 5;
    int sub = lane >> 3, cls = lane & 7;
    int node = warpg * 4 + sub;
    float acc = 0.f;
    if (node < Nn) {
        const float* ur = u + (size_t)node * 64;
#pragma unroll 8
        for (int k = 0; k < 64; k++) acc += ur[k] * W[k * 8 + cls];
        acc += b[cls];
    }
    float mx = acc;
#pragma unroll
    for (int o = 4; o >= 1; o >>= 1) mx = fmaxf(mx, __shfl_xor_sync(0xffffffffu, mx, o));
    float se = expf(acc - mx);
#pragma unroll
    for (int o = 4; o >= 1; o >>= 1) se += __shfl_xor_sync(0xffffffffu, se, o);
    if (node < Nn) out[(size_t)node * 8 + cls] = acc - mx - logf(se);
}

// ---------------- host orchestration ----------------
extern "C" void kernel_launch(void* const* d_in, const int* in_sizes, int n_in,
                              void* d_out, int out_size)
{
    const float* x     = (const float*)d_in[0];
    const void*  ei    = d_in[1];
    const float* W1    = (const float*)d_in[2];
    const float* asr1  = (const float*)d_in[3];
    const float* adt1  = (const float*)d_in[4];
    const float* b1    = (const float*)d_in[5];
    const float* bn1g  = (const float*)d_in[6];
    const float* bn1b  = (const float*)d_in[7];
    const float* bn1m  = (const float*)d_in[8];
    const float* bn1v  = (const float*)d_in[9];
    const float* W2    = (const float*)d_in[10];
    const float* asr2  = (const float*)d_in[11];
    const float* adt2  = (const float*)d_in[12];
    const float* b2    = (const float*)d_in[13];
    const float* bn2g  = (const float*)d_in[14];
    const float* bn2b  = (const float*)d_in[15];
    const float* bn2m  = (const float*)d_in[16];
    const float* bn2v  = (const float*)d_in[17];
    const float* W3    = (const float*)d_in[18];
    const float* asr3  = (const float*)d_in[19];
    const float* adt3  = (const float*)d_in[20];
    const float* b3    = (const float*)d_in[21];
    const float* skipW = (const float*)d_in[22];
    const float* skipb = (const float*)d_in[23];
    const float* l1W   = (const float*)d_in[24];
    const float* l1b   = (const float*)d_in[25];
    const float* l2W   = (const float*)d_in[26];
    const float* l2b   = (const float*)d_in[27];

    int Nn = in_sizes[0] / 64;
    int E  = in_sizes[1] / 2;
    if (Nn > MAXN) Nn = MAXN;
    if (E > MAXE) E = MAXE;

    float *bufA, *bufB;
    cudaGetSymbolAddress((void**)&bufA, g_bufA);
    cudaGetSymbolAddress((void**)&bufB, g_bufB);

    int eb = (E + 255) / 256;
    int nb = (Nn + 1 + 255) / 256;
    int sb = (Nn + 1023) / 1024;      // scan blocks (<= 49)

    // --- edge dtype normalization + CSR build ---
    detect_kernel<<<1, 256>>>((const unsigned int*)ei, E);
    zero_kernel<<<nb, 256>>>(Nn);
    conv_deg_kernel<<<eb, 256>>>(ei, E, Nn);
    scan_blocks<<<sb, 1024>>>(Nn);
    scan_tops<<<1, 64>>>(sb);
    scan_add<<<sb, 1024>>>(Nn);
    scat_kernel<<<eb, 256>>>(E);

    int gb = (Nn + 63) / 64;
    int ab = (Nn + 7) / 8;            // 8 warps per block

    // --- layer 1: 64 -> 3x64 (alpha fused into GEMM epilogue) ---
    gemm_kernel<192, 3><<<gb, 256>>>(x, W1, bufA, Nn, 64, 0, nullptr, nullptr, nullptr, asr1, adt1);
    agg_kernel<3><<<ab, 256>>>(bufA, b1, bn1g, bn1b, bn1m, bn1v, bufB, Nn, 0);

    // --- layer 2: 192 -> 2x64 ---
    gemm_kernel<128, 2><<<gb, 256>>>(bufB, W2, bufA, Nn, 192, 0, nullptr, nullptr, nullptr, asr2, adt2);
    agg_kernel<2><<<ab, 256>>>(bufA, b2, bn2g, bn2b, bn2m, bn2v, bufB, Nn, 0);

    // --- layer 3: 128 -> 64 (raw aggregation; b3 folded into skip epilogue) ---
    gemm_kernel<64, 1><<<gb, 256>>>(bufB, W3, bufA, Nn, 128, 0, nullptr, nullptr, nullptr, asr3, adt3);
    agg_kernel<1><<<ab, 256>>>(bufA, nullptr, nullptr, nullptr, nullptr, nullptr, bufB, Nn, 1);

    // --- skip: t = x@skipW + skip_b + b3 + agg3 ---
    gemm_kernel<64, 0><<<gb, 256>>>(x, skipW, bufA, Nn, 64, 1, skipb, b3, bufB, nullptr, nullptr);
    // --- lin1: u = elu(t@l1W + l1b) ---
    gemm_kernel<64, 0><<<gb, 256>>>(bufA, l1W, bufB, Nn, 64, 2, l1b, nullptr, nullptr, nullptr, nullptr);
    // --- lin2 + log_softmax ---
    head_kernel<<<(Nn * 8 + 255) / 256, 256>>>(bufB, l2W, l2b, (float*)d_out, Nn);
}

// round 14
// speedup vs baseline: 1.3717x; 1.0550x over previous
#include <cuda_runtime.h>
#include <cuda_bf16.h>
#include <math.h>

#define MAXN 50048
#define MAXE 800256

// ---------------- scratch (static device globals; no allocs) ----------------
__device__ float g_bufA[MAXN * 192];
__device__ float g_bufB[MAXN * 192];
__device__ float g_as[MAXN * 3];
__device__ float g_ad[MAXN * 3];
__device__ int   g_deg[MAXN];
__device__ int   g_cnt[MAXN];
__device__ int   g_offs[MAXN + 1];
__device__ int   g_csr[MAXE];
__device__ int   g_src[MAXE];
__device__ int   g_dst[MAXE];
__device__ int   g_bsum[64];
__device__ int   g_btop[64];
__device__ unsigned int g_mxbits[9];   // [layer*3 + head] encoded float max
__device__ int   g_is64;

// ---------------- packed f32x2 helpers ----------------
__device__ __forceinline__ unsigned long long pk2(float lo, float hi) {
    unsigned long long r;
    asm("mov.b64 %0, {%1, %2};" : "=l"(r) : "f"(lo), "f"(hi));
    return r;
}
__device__ __forceinline__ void upk2(float& lo, float& hi, unsigned long long v) {
    asm("mov.b64 {%0, %1}, %2;" : "=f"(lo), "=f"(hi) : "l"(v));
}
__device__ __forceinline__ unsigned long long fma2(unsigned long long a,
                                                   unsigned long long b,
                                                   unsigned long long c) {
    unsigned long long d;
    asm("fma.rn.f32x2 %0, %1, %2, %3;" : "=l"(d) : "l"(a), "l"(b), "l"(c));
    return d;
}

// monotone float<->uint encoding for atomicMax on floats
__device__ __forceinline__ unsigned int fenc(float f) {
    unsigned int b = __float_as_uint(f);
    return (b & 0x80000000u) ? ~b : (b | 0x80000000u);
}
__device__ __forceinline__ float fdec(unsigned int u) {
    unsigned int b = (u & 0x80000000u) ? (u ^ 0x80000000u) : ~u;
    return __uint_as_float(b);
}

// ---------------- edge dtype detection + normalization ----------------
__global__ void detect_kernel(const unsigned int* __restrict__ p, int E) {
    __shared__ int any;
    if (threadIdx.x == 0) any = 0;
    __syncthreads();
    int nsamp = min(E, 4096);
    for (int i = threadIdx.x; i < nsamp; i += 256)
        if (p[2 * i + 1] != 0u) any = 1;
    __syncthreads();
    if (threadIdx.x == 0) g_is64 = (any == 0) ? 1 : 0;
}

__global__ void zero_kernel(int n) {
    int i = blockIdx.x * blockDim.x + threadIdx.x;
    if (i < n) { g_deg[i] = 0; g_cnt[i] = 0; }
    if (i < 9) g_mxbits[i] = 0u;   // encoded -inf
}

// convert + clamp + degree histogram in one pass
__global__ void conv_deg_kernel(const void* __restrict__ ei, int E, int Nn) {
    int i = blockIdx.x * blockDim.x + threadIdx.x;
    if (i >= E) return;
    int s, d;
    if (g_is64) {
        const long long* p = (const long long*)ei;
        s = (int)p[i];
        d = (int)p[(size_t)E + i];
    } else {
        const int* p = (const int*)ei;
        s = p[i];
        d = p[E + i];
    }
    s = min(max(s, 0), Nn - 1);
    d = min(max(d, 0), Nn - 1);
    g_src[i] = s;
    g_dst[i] = d;
    atomicAdd(&g_deg[d], 1);
}

// ---------------- hierarchical scan: offs = exclusive-prefix(deg) ----------------
__global__ void scan_blocks(int n) {
    __shared__ int sm[1024];
    int tid = threadIdx.x;
    int i = blockIdx.x * 1024 + tid;
    int v = (i < n) ? g_deg[i] : 0;
    sm[tid] = v;
    __syncthreads();
#pragma unroll
    for (int d = 1; d < 1024; d <<= 1) {
        int t = (tid >= d) ? sm[tid - d] : 0;
        __syncthreads();
        sm[tid] += t;
        __syncthreads();
    }
    if (i < n) g_offs[i + 1] = sm[tid];
    if (tid == 1023) g_bsum[blockIdx.x] = sm[1023];
}

__global__ void scan_tops(int nb) {
    __shared__ int sm[64];
    int tid = threadIdx.x;
    sm[tid] = (tid < nb) ? g_bsum[tid] : 0;
    __syncthreads();
#pragma unroll
    for (int d = 1; d < 64; d <<= 1) {
        int t = (tid >= d) ? sm[tid - d] : 0;
        __syncthreads();
        sm[tid] += t;
        __syncthreads();
    }
    g_btop[tid] = (tid == 0) ? 0 : sm[tid - 1];
}

__global__ void scan_add(int n) {
    int i = blockIdx.x * 1024 + threadIdx.x;
    if (i < n) g_offs[i + 1] += g_btop[blockIdx.x];
    if (i == 0) g_offs[0] = 0;
}

__global__ void scat_kernel(int E) {
    int i = blockIdx.x * blockDim.x + threadIdx.x;
    if (i < E) {
        int d = g_dst[i];
        int pos = g_offs[d] + atomicAdd(&g_cnt[d], 1);
        g_csr[pos] = g_src[i];
    }
}

// ---------------- per-head global max of g_as (for softmax shift) ----------------
template <int H>
__global__ void amax_kernel(int Nn, int layer) {
    __shared__ float sm[8][H];
    int tid = threadIdx.x;
    int lane = tid & 31, wid = tid >> 5;
    float mx[H];
#pragma unroll
    for (int h = 0; h < H; h++) mx[h] = -1e30f;
    for (int i = blockIdx.x * 256 + tid; i < Nn; i += gridDim.x * 256) {
#pragma unroll
        for (int h = 0; h < H; h++) mx[h] = fmaxf(mx[h], g_as[i * H + h]);
    }
#pragma unroll
    for (int o = 16; o >= 1; o >>= 1)
#pragma unroll
        for (int h = 0; h < H; h++)
            mx[h] = fmaxf(mx[h], __shfl_xor_sync(0xffffffffu, mx[h], o));
    if (lane == 0)
#pragma unroll
        for (int h = 0; h < H; h++) sm[wid][h] = mx[h];
    __syncthreads();
    if (wid == 0 && lane < H) {
        float v = sm[0][lane];
#pragma unroll
        for (int w = 1; w < 8; w++) v = fmaxf(v, sm[w][lane]);
        atomicMax(&g_mxbits[layer * 3 + lane], fenc(v));
    }
}

// ---------------- f32x2-packed SGEMM with fused alpha epilogue ----------------
// Y[M,OUT] = X[M,K] @ W[K,OUT] (+ epilogue). Requires K % 32 == 0.
// HEADS>0: also writes g_as/g_ad = per-head dot(h_row, a_src/a_dst).
// epi: 0 = none; 1 = + bias_a + bias_b + extra; 2 = elu(+ bias_a)
template <int OUT, int HEADS>
__global__ void __launch_bounds__(256) gemm_kernel(
    const float* __restrict__ X, const float* __restrict__ W, float* __restrict__ Y,
    int M, int K, int epi,
    const float* __restrict__ bias_a, const float* __restrict__ bias_b,
    const float* __restrict__ extra,
    const float* __restrict__ a_src, const float* __restrict__ a_dst)
{
    constexpr int TN2 = OUT / 32;
    constexpr int HM = (HEADS > 0) ? HEADS : 1;
    __shared__ __align__(16) float xsT[32][68];   // [k][row], row-padded to 68
    __shared__ __align__(16) float ws[32][OUT];
    __shared__ float sav[OUT], sdv[OUT];

    int tid = threadIdx.x;
    int tx = tid & 15, ty = tid >> 4;
    int row0 = blockIdx.x * 64;

    if (HEADS > 0) {
        for (int i = tid; i < OUT; i += 256) { sav[i] = a_src[i]; sdv[i] = a_dst[i]; }
    }

    unsigned long long acc2[4][TN2];
#pragma unroll
    for (int i = 0; i < 4; i++)
#pragma unroll
        for (int j = 0; j < TN2; j++) acc2[i][j] = 0ULL;

    for (int k0 = 0; k0 < K; k0 += 32) {
#pragma unroll
        for (int idx = tid; idx < 64 * 32; idx += 256) {
            int r = idx >> 5, kk = idx & 31;
            int gr = row0 + r;
            xsT[kk][r] = (gr < M) ? X[(size_t)gr * K + k0 + kk] : 0.f;
        }
#pragma unroll
        for (int idx = tid; idx < 32 * OUT; idx += 256) {
            int kk = idx / OUT, c = idx % OUT;
            ws[kk][c] = W[(size_t)(k0 + kk) * OUT + c];
        }
        __syncthreads();
#pragma unroll 8
        for (int kk = 0; kk < 32; kk++) {
            float4 av = *reinterpret_cast<const float4*>(&xsT[kk][ty * 4]);
            unsigned long long a0 = pk2(av.x, av.x);
            unsigned long long a1 = pk2(av.y, av.y);
            unsigned long long a2 = pk2(av.z, av.z);
            unsigned long long a3 = pk2(av.w, av.w);
#pragma unroll
            for (int jj = 0; jj < TN2; jj++) {
                unsigned long long bw = *reinterpret_cast<const unsigned long long*>(
                    &ws[kk][2 * tx + 32 * jj]);
                acc2[0][jj] = fma2(a0, bw, acc2[0][jj]);
                acc2[1][jj] = fma2(a1, bw, acc2[1][jj]);
                acc2[2][jj] = fma2(a2, bw, acc2[2][jj]);
                acc2[3][jj] = fma2(a3, bw, acc2[3][jj]);
            }
        }
        __syncthreads();
    }

#pragma unroll
    for (int i = 0; i < 4; i++) {
        int gr = row0 + ty * 4 + i;
        float asum[HM], dsum[HM];
#pragma unroll
        for (int h = 0; h < HM; h++) { asum[h] = 0.f; dsum[h] = 0.f; }
#pragma unroll
        for (int jj = 0; jj < TN2; jj++) {
            float lo, hi;
            upk2(lo, hi, acc2[i][jj]);
            int c0 = 2 * tx + 32 * jj;
            if (epi == 1) {
                if (gr < M) {
                    lo += bias_a[c0] + bias_b[c0] + extra[(size_t)gr * OUT + c0];
                    hi += bias_a[c0 + 1] + bias_b[c0 + 1] + extra[(size_t)gr * OUT + c0 + 1];
                }
            } else if (epi == 2) {
                lo += bias_a[c0];
                hi += bias_a[c0 + 1];
                lo = (lo > 0.f) ? lo : expm1f(lo);
                hi = (hi > 0.f) ? hi : expm1f(hi);
            }
            if (gr < M) {
                Y[(size_t)gr * OUT + c0] = lo;
                Y[(size_t)gr * OUT + c0 + 1] = hi;
            }
            if (HEADS > 0) {
                int h = jj >> 1;   // 64 cols per head, 32 per jj
                asum[h] += lo * sav[c0] + hi * sav[c0 + 1];
                dsum[h] += lo * sdv[c0] + hi * sdv[c0 + 1];
            }
        }
        if (HEADS > 0) {
#pragma unroll
            for (int h = 0; h < HM; h++) {
#pragma unroll
                for (int o = 8; o >= 1; o >>= 1) {
                    asum[h] += __shfl_xor_sync(0xffffffffu, asum[h], o);
                    dsum[h] += __shfl_xor_sync(0xffffffffu, dsum[h], o);
                }
            }
            if (tx == 0 && gr < M) {
#pragma unroll
                for (int h = 0; h < HM; h++) {
                    g_as[gr * HEADS + h] = asum[h];
                    g_ad[gr * HEADS + h] = dsum[h];
                }
            }
        }
    }
}

// ---------------- softmax-aggregation: single pass, global-max shift ----------------
// m_h = lrelu(global_max(as_h) + adn_h) >= per-dst max after lrelu (monotone),
// so exp(e - m) <= 1; softmax ratio identical to reference.
// mode 0: out = elu(BN(acc + bias)); mode 1: out = acc (raw, layer 3)
template <int H>
__global__ void __launch_bounds__(256) agg_kernel(
    const float* __restrict__ hpre,
    const float* __restrict__ bias,
    const float* __restrict__ bng, const float* __restrict__ bnb,
    const float* __restrict__ bnm, const float* __restrict__ bnv,
    float* __restrict__ out, int Nn, int mode, int layer)
{
    int warp = (blockIdx.x * 256 + threadIdx.x) >> 5;
    int lane = threadIdx.x & 31;
    if (warp >= Nn) return;
    int start = g_offs[warp], end = g_offs[warp + 1];

    float adn[H], m[H];
#pragma unroll
    for (int h = 0; h < H; h++) {
        adn[h] = g_ad[warp * H + h];
        float e = fdec(g_mxbits[layer * 3 + h]) + adn[h];
        m[h] = (e > 0.f) ? e : 0.2f * e;
    }

    float2 acc[H];
    float ssum[H];
#pragma unroll
    for (int h = 0; h < H; h++) { acc[h].x = 0.f; acc[h].y = 0.f; ssum[h] = 0.f; }

    for (int base = start; base < end; base += 32) {
        int nb = min(32, end - base);
        int src_l = 0;
        float w_l[H];
#pragma unroll
        for (int h = 0; h < H; h++) w_l[h] = 0.f;
        if (base + lane < end) {
            src_l = g_csr[base + lane];
#pragma unroll
            for (int h = 0; h < H; h++) {
                float e = g_as[src_l * H + h] + adn[h];
                e = (e > 0.f) ? e : 0.2f * e;
                float w = __expf(e - m[h]);
                w_l[h] = w;
                ssum[h] += w;
            }
        }
        for (int j = 0; j < nb; j++) {
            int src = __shfl_sync(0xffffffffu, src_l, j);
            const float2* hr = reinterpret_cast<const float2*>(hpre + (size_t)src * (H * 64));
#pragma unroll
            for (int h = 0; h < H; h++) {
                float w = __shfl_sync(0xffffffffu, w_l[h], j);
                float2 v = hr[h * 32 + lane];
                acc[h].x += w * v.x;
                acc[h].y += w * v.y;
            }
        }
    }

#pragma unroll
    for (int o = 16; o >= 1; o >>= 1)
#pragma unroll
        for (int h = 0; h < H; h++)
            ssum[h] += __shfl_xor_sync(0xffffffffu, ssum[h], o);

    float2* orow = reinterpret_cast<float2*>(out + (size_t)warp * (H * 64));
#pragma unroll
    for (int h = 0; h < H; h++) {
        float inv = 1.f / (ssum[h] + 1e-16f);
        int c = h * 64 + 2 * lane;
        float vx = acc[h].x * inv;
        float vy = acc[h].y * inv;
        if (mode == 0) {
            vx += bias[c];
            vy += bias[c + 1];
            vx = (vx - bnm[c]) * (bng[c] * rsqrtf(bnv[c] + 1e-5f)) + bnb[c];
            vy = (vy - bnm[c + 1]) * (bng[c + 1] * rsqrtf(bnv[c + 1] + 1e-5f)) + bnb[c + 1];
            vx = (vx > 0.f) ? vx : expm1f(vx);
            vy = (vy > 0.f) ? vy : expm1f(vy);
        }
        float2 o2; o2.x = vx; o2.y = vy;
        orow[h * 32 + lane] = o2;
    }
}

// ---------------- head: logits = u @ W2[64,8] + b, then log_softmax ----------------
__global__ void head_kernel(const float* __restrict__ u, const float* __restrict__ W,
                            const float* __restrict__ b, float* __restrict__ out, int Nn)
{
    int gtid = blockIdx.x * blockDim.x + threadIdx.x;
    int lane = threadIdx.x & 31;
    int warpg = gtid >> 5;
    int sub = lane >> 3, cls = lane & 7;
    int node = warpg * 4 + sub;
    float acc = 0.f;
    if (node < Nn) {
        const float* ur = u + (size_t)node * 64;
#pragma unroll 8
        for (int k = 0; k < 64; k++) acc += ur[k] * W[k * 8 + cls];
        acc += b[cls];
    }
    float mx = acc;
#pragma unroll
    for (int o = 4; o >= 1; o >>= 1) mx = fmaxf(mx, __shfl_xor_sync(0xffffffffu, mx, o));
    float se = expf(acc - mx);
#pragma unroll
    for (int o = 4; o >= 1; o >>= 1) se += __shfl_xor_sync(0xffffffffu, se, o);
    if (node < Nn) out[(size_t)node * 8 + cls] = acc - mx - logf(se);
}

// ---------------- host orchestration ----------------
extern "C" void kernel_launch(void* const* d_in, const int* in_sizes, int n_in,
                              void* d_out, int out_size)
{
    const float* x     = (const float*)d_in[0];
    const void*  ei    = d_in[1];
    const float* W1    = (const float*)d_in[2];
    const float* asr1  = (const float*)d_in[3];
    const float* adt1  = (const float*)d_in[4];
    const float* b1    = (const float*)d_in[5];
    const float* bn1g  = (const float*)d_in[6];
    const float* bn1b  = (const float*)d_in[7];
    const float* bn1m  = (const float*)d_in[8];
    const float* bn1v  = (const float*)d_in[9];
    const float* W2    = (const float*)d_in[10];
    const float* asr2  = (const float*)d_in[11];
    const float* adt2  = (const float*)d_in[12];
    const float* b2    = (const float*)d_in[13];
    const float* bn2g  = (const float*)d_in[14];
    const float* bn2b  = (const float*)d_in[15];
    const float* bn2m  = (const float*)d_in[16];
    const float* bn2v  = (const float*)d_in[17];
    const float* W3    = (const float*)d_in[18];
    const float* asr3  = (const float*)d_in[19];
    const float* adt3  = (const float*)d_in[20];
    const float* b3    = (const float*)d_in[21];
    const float* skipW = (const float*)d_in[22];
    const float* skipb = (const float*)d_in[23];
    const float* l1W   = (const float*)d_in[24];
    const float* l1b   = (const float*)d_in[25];
    const float* l2W   = (const float*)d_in[26];
    const float* l2b   = (const float*)d_in[27];

    int Nn = in_sizes[0] / 64;
    int E  = in_sizes[1] / 2;
    if (Nn > MAXN) Nn = MAXN;
    if (E > MAXE) E = MAXE;

    float *bufA, *bufB;
    cudaGetSymbolAddress((void**)&bufA, g_bufA);
    cudaGetSymbolAddress((void**)&bufB, g_bufB);

    int eb = (E + 255) / 256;
    int nb = (Nn + 1 + 255) / 256;
    int sb = (Nn + 1023) / 1024;      // scan blocks (<= 49)
    int gb = (Nn + 63) / 64;
    int ab = (Nn + 7) / 8;            // 8 warps per block
    int mb = 64;                      // amax blocks

    // launches 1-3: dtype + zero + conv/deg
    detect_kernel<<<1, 256>>>((const unsigned int*)ei, E);
    zero_kernel<<<nb, 256>>>(Nn);
    conv_deg_kernel<<<eb, 256>>>(ei, E, Nn);

    // launch 4 (profiled slot): layer-1 GEMM — independent of CSR build
    gemm_kernel<192, 3><<<gb, 256>>>(x, W1, bufA, Nn, 64, 0, nullptr, nullptr, nullptr, asr1, adt1);

    // CSR build
    scan_blocks<<<sb, 1024>>>(Nn);
    scan_tops<<<1, 64>>>(sb);
    scan_add<<<sb, 1024>>>(Nn);
    scat_kernel<<<eb, 256>>>(E);

    // --- layer 1 ---
    amax_kernel<3><<<mb, 256>>>(Nn, 0);
    agg_kernel<3><<<ab, 256>>>(bufA, b1, bn1g, bn1b, bn1m, bn1v, bufB, Nn, 0, 0);

    // --- layer 2: 192 -> 2x64 ---
    gemm_kernel<128, 2><<<gb, 256>>>(bufB, W2, bufA, Nn, 192, 0, nullptr, nullptr, nullptr, asr2, adt2);
    amax_kernel<2><<<mb, 256>>>(Nn, 1);
    agg_kernel<2><<<ab, 256>>>(bufA, b2, bn2g, bn2b, bn2m, bn2v, bufB, Nn, 0, 1);

    // --- layer 3: 128 -> 64 (raw aggregation; b3 folded into skip epilogue) ---
    gemm_kernel<64, 1><<<gb, 256>>>(bufB, W3, bufA, Nn, 128, 0, nullptr, nullptr, nullptr, asr3, adt3);
    amax_kernel<1><<<mb, 256>>>(Nn, 2);
    agg_kernel<1><<<ab, 256>>>(bufA, nullptr, nullptr, nullptr, nullptr, nullptr, bufB, Nn, 1, 2);

    // --- skip: t = x@skipW + skip_b + b3 + agg3 ---
    gemm_kernel<64, 0><<<gb, 256>>>(x, skipW, bufA, Nn, 64, 1, skipb, b3, bufB, nullptr, nullptr);
    // --- lin1: u = elu(t@l1W + l1b) ---
    gemm_kernel<64, 0><<<gb, 256>>>(bufA, l1W, bufB, Nn, 64, 2, l1b, nullptr, nullptr, nullptr, nullptr);
    // --- lin2 + log_softmax ---
    head_kernel<<<(Nn * 8 + 255) / 256, 256>>>(bufB, l2W, l2b, (float*)d_out, Nn);
}

// round 17
// speedup vs baseline: 1.3789x; 1.0053x over previous
#include <cuda_runtime.h>
#include <cuda_bf16.h>
#include <math.h>

#define MAXN 50048
#define MAXE 800256

// ---------------- scratch (static device globals; no allocs) ----------------
__device__ float g_bufA[MAXN * 192];
__device__ float g_bufB[MAXN * 192];
__device__ float g_as[MAXN * 3];
__device__ float g_ad[MAXN * 3];
__device__ int   g_deg[MAXN];
__device__ int   g_cnt[MAXN];
__device__ int   g_offs[MAXN + 1];
__device__ int   g_csr[MAXE];
__device__ int   g_src[MAXE];
__device__ int   g_dst[MAXE];
__device__ int   g_bsum[64];
__device__ int   g_btop[64];
__device__ unsigned int g_mxbits[9];   // [layer*3 + head] encoded float max
__device__ int   g_is64;

// ---------------- packed f32x2 helpers ----------------
__device__ __forceinline__ unsigned long long pk2(float lo, float hi) {
    unsigned long long r;
    asm("mov.b64 %0, {%1, %2};" : "=l"(r) : "f"(lo), "f"(hi));
    return r;
}
__device__ __forceinline__ void upk2(float& lo, float& hi, unsigned long long v) {
    asm("mov.b64 {%0, %1}, %2;" : "=f"(lo), "=f"(hi) : "l"(v));
}
__device__ __forceinline__ unsigned long long fma2(unsigned long long a,
                                                   unsigned long long b,
                                                   unsigned long long c) {
    unsigned long long d;
    asm("fma.rn.f32x2 %0, %1, %2, %3;" : "=l"(d) : "l"(a), "l"(b), "l"(c));
    return d;
}

// monotone float<->uint encoding for atomicMax on floats
__device__ __forceinline__ unsigned int fenc(float f) {
    unsigned int b = __float_as_uint(f);
    return (b & 0x80000000u) ? ~b : (b | 0x80000000u);
}
__device__ __forceinline__ float fdec(unsigned int u) {
    unsigned int b = (u & 0x80000000u) ? (u ^ 0x80000000u) : ~u;
    return __uint_as_float(b);
}

// ---------------- edge dtype detection + normalization ----------------
__global__ void detect_kernel(const unsigned int* __restrict__ p, int E) {
    __shared__ int any;
    if (threadIdx.x == 0) any = 0;
    __syncthreads();
    int nsamp = min(E, 4096);
    for (int i = threadIdx.x; i < nsamp; i += 256)
        if (p[2 * i + 1] != 0u) any = 1;
    __syncthreads();
    if (threadIdx.x == 0) g_is64 = (any == 0) ? 1 : 0;
}

__global__ void zero_kernel(int n) {
    int i = blockIdx.x * blockDim.x + threadIdx.x;
    if (i < n) { g_deg[i] = 0; g_cnt[i] = 0; }
    if (i < 9) g_mxbits[i] = 0u;   // encoded -inf
}

// convert + clamp + degree histogram in one pass
__global__ void conv_deg_kernel(const void* __restrict__ ei, int E, int Nn) {
    int i = blockIdx.x * blockDim.x + threadIdx.x;
    if (i >= E) return;
    int s, d;
    if (g_is64) {
        const long long* p = (const long long*)ei;
        s = (int)p[i];
        d = (int)p[(size_t)E + i];
    } else {
        const int* p = (const int*)ei;
        s = p[i];
        d = p[E + i];
    }
    s = min(max(s, 0), Nn - 1);
    d = min(max(d, 0), Nn - 1);
    g_src[i] = s;
    g_dst[i] = d;
    atomicAdd(&g_deg[d], 1);
}

// ---------------- hierarchical scan: offs = exclusive-prefix(deg) ----------------
__global__ void scan_blocks(int n) {
    __shared__ int sm[1024];
    int tid = threadIdx.x;
    int i = blockIdx.x * 1024 + tid;
    int v = (i < n) ? g_deg[i] : 0;
    sm[tid] = v;
    __syncthreads();
#pragma unroll
    for (int d = 1; d < 1024; d <<= 1) {
        int t = (tid >= d) ? sm[tid - d] : 0;
        __syncthreads();
        sm[tid] += t;
        __syncthreads();
    }
    if (i < n) g_offs[i + 1] = sm[tid];
    if (tid == 1023) g_bsum[blockIdx.x] = sm[1023];
}

__global__ void scan_tops(int nb) {
    __shared__ int sm[64];
    int tid = threadIdx.x;
    sm[tid] = (tid < nb) ? g_bsum[tid] : 0;
    __syncthreads();
#pragma unroll
    for (int d = 1; d < 64; d <<= 1) {
        int t = (tid >= d) ? sm[tid - d] : 0;
        __syncthreads();
        sm[tid] += t;
        __syncthreads();
    }
    g_btop[tid] = (tid == 0) ? 0 : sm[tid - 1];
}

__global__ void scan_add(int n) {
    int i = blockIdx.x * 1024 + threadIdx.x;
    if (i < n) g_offs[i + 1] += g_btop[blockIdx.x];
    if (i == 0) g_offs[0] = 0;
}

__global__ void scat_kernel(int E) {
    int i = blockIdx.x * blockDim.x + threadIdx.x;
    if (i < E) {
        int d = g_dst[i];
        int pos = g_offs[d] + atomicAdd(&g_cnt[d], 1);
        g_csr[pos] = g_src[i];
    }
}

// ---------------- f32x2-packed SGEMM, LDS.128 B loads, fused alpha + amax ----------------
// Y[M,OUT] = X[M,K] @ W[K,OUT] (+ epilogue). Requires K % 32 == 0, OUT % 64 == 0.
// Thread tx owns 4 consecutive columns per group j: c = 4*tx + 64*j (group j == head j).
// HEADS>0: writes g_as/g_ad and atomicMax's per-head global max into g_mxbits[layer].
// epi: 0 = none; 1 = + bias_a + bias_b + extra; 2 = elu(+ bias_a)
template <int OUT, int HEADS>
__global__ void __launch_bounds__(256) gemm_kernel(
    const float* __restrict__ X, const float* __restrict__ W, float* __restrict__ Y,
    int M, int K, int epi,
    const float* __restrict__ bias_a, const float* __restrict__ bias_b,
    const float* __restrict__ extra,
    const float* __restrict__ a_src, const float* __restrict__ a_dst,
    int layer)
{
    constexpr int NJ = OUT / 64;
    constexpr int HM = (HEADS > 0) ? HEADS : 1;
    __shared__ __align__(16) float xsT[32][68];   // [k][row], row-padded to 68
    __shared__ __align__(16) float ws[32][OUT];
    __shared__ float sav[OUT], sdv[OUT];
    __shared__ unsigned int smx[HM];

    int tid = threadIdx.x;
    int tx = tid & 15, ty = tid >> 4;
    int row0 = blockIdx.x * 64;

    if (HEADS > 0) {
        for (int i = tid; i < OUT; i += 256) { sav[i] = a_src[i]; sdv[i] = a_dst[i]; }
        if (tid < HM) smx[tid] = 0u;   // encoded -inf
    }

    unsigned long long acc2[4][NJ][2];
#pragma unroll
    for (int i = 0; i < 4; i++)
#pragma unroll
        for (int j = 0; j < NJ; j++) { acc2[i][j][0] = 0ULL; acc2[i][j][1] = 0ULL; }

    for (int k0 = 0; k0 < K; k0 += 32) {
#pragma unroll
        for (int idx = tid; idx < 64 * 32; idx += 256) {
            int r = idx >> 5, kk = idx & 31;
            int gr = row0 + r;
            xsT[kk][r] = (gr < M) ? X[(size_t)gr * K + k0 + kk] : 0.f;
        }
#pragma unroll
        for (int idx = tid; idx < 32 * OUT; idx += 256) {
            int kk = idx / OUT, c = idx % OUT;
            ws[kk][c] = W[(size_t)(k0 + kk) * OUT + c];
        }
        __syncthreads();
#pragma unroll 8
        for (int kk = 0; kk < 32; kk++) {
            float4 av = *reinterpret_cast<const float4*>(&xsT[kk][ty * 4]);
            unsigned long long a0 = pk2(av.x, av.x);
            unsigned long long a1 = pk2(av.y, av.y);
            unsigned long long a2 = pk2(av.z, av.z);
            unsigned long long a3 = pk2(av.w, av.w);
#pragma unroll
            for (int j = 0; j < NJ; j++) {
                ulonglong2 bw = *reinterpret_cast<const ulonglong2*>(
                    &ws[kk][4 * tx + 64 * j]);
                acc2[0][j][0] = fma2(a0, bw.x, acc2[0][j][0]);
                acc2[0][j][1] = fma2(a0, bw.y, acc2[0][j][1]);
                acc2[1][j][0] = fma2(a1, bw.x, acc2[1][j][0]);
                acc2[1][j][1] = fma2(a1, bw.y, acc2[1][j][1]);
                acc2[2][j][0] = fma2(a2, bw.x, acc2[2][j][0]);
                acc2[2][j][1] = fma2(a2, bw.y, acc2[2][j][1]);
                acc2[3][j][0] = fma2(a3, bw.x, acc2[3][j][0]);
                acc2[3][j][1] = fma2(a3, bw.y, acc2[3][j][1]);
            }
        }
        __syncthreads();
    }

    float lmax[HM];
#pragma unroll
    for (int h = 0; h < HM; h++) lmax[h] = -1e30f;

#pragma unroll
    for (int i = 0; i < 4; i++) {
        int gr = row0 + ty * 4 + i;
        float asum[HM], dsum[HM];
#pragma unroll
        for (int h = 0; h < HM; h++) { asum[h] = 0.f; dsum[h] = 0.f; }
#pragma unroll
        for (int j = 0; j < NJ; j++) {
#pragma unroll
            for (int p = 0; p < 2; p++) {
                float lo, hi;
                upk2(lo, hi, acc2[i][j][p]);
                int c0 = 4 * tx + 64 * j + 2 * p;
                if (epi == 1) {
                    if (gr < M) {
                        lo += bias_a[c0] + bias_b[c0] + extra[(size_t)gr * OUT + c0];
                        hi += bias_a[c0 + 1] + bias_b[c0 + 1] + extra[(size_t)gr * OUT + c0 + 1];
                    }
                } else if (epi == 2) {
                    lo += bias_a[c0];
                    hi += bias_a[c0 + 1];
                    lo = (lo > 0.f) ? lo : expm1f(lo);
                    hi = (hi > 0.f) ? hi : expm1f(hi);
                }
                if (gr < M) {
                    Y[(size_t)gr * OUT + c0] = lo;
                    Y[(size_t)gr * OUT + c0 + 1] = hi;
                }
                if (HEADS > 0) {
                    asum[j] += lo * sav[c0] + hi * sav[c0 + 1];
                    dsum[j] += lo * sdv[c0] + hi * sdv[c0 + 1];
                }
            }
        }
        if (HEADS > 0) {
#pragma unroll
            for (int h = 0; h < HM; h++) {
#pragma unroll
                for (int o = 8; o >= 1; o >>= 1) {
                    asum[h] += __shfl_xor_sync(0xffffffffu, asum[h], o);
                    dsum[h] += __shfl_xor_sync(0xffffffffu, dsum[h], o);
                }
            }
            if (gr < M) {
#pragma unroll
                for (int h = 0; h < HM; h++) lmax[h] = fmaxf(lmax[h], asum[h]);
                if (tx == 0) {
#pragma unroll
                    for (int h = 0; h < HM; h++) {
                        g_as[gr * HEADS + h] = asum[h];
                        g_ad[gr * HEADS + h] = dsum[h];
                    }
                }
            }
        }
    }

    if (HEADS > 0) {
        if (tx == 0) {
#pragma unroll
            for (int h = 0; h < HM; h++) atomicMax(&smx[h], fenc(lmax[h]));
        }
        __syncthreads();
        if (tid < HM) atomicMax(&g_mxbits[layer * 3 + tid], smx[tid]);
    }
}

// ---------------- softmax-aggregation: single pass, global-max shift ----------------
// m_h = lrelu(global_max(as_h) + adn_h) >= per-dst max after lrelu (monotone),
// so exp(e - m) <= 1; softmax ratio identical to reference.
// mode 0: out = elu(BN(acc + bias)); mode 1: out = acc (raw, layer 3)
template <int H>
__global__ void __launch_bounds__(256) agg_kernel(
    const float* __restrict__ hpre,
    const float* __restrict__ bias,
    const float* __restrict__ bng, const float* __restrict__ bnb,
    const float* __restrict__ bnm, const float* __restrict__ bnv,
    float* __restrict__ out, int Nn, int mode, int layer)
{
    int warp = (blockIdx.x * 256 + threadIdx.x) >> 5;
    int lane = threadIdx.x & 31;
    if (warp >= Nn) return;
    int start = g_offs[warp], end = g_offs[warp + 1];

    float adn[H], m[H];
#pragma unroll
    for (int h = 0; h < H; h++) {
        adn[h] = g_ad[warp * H + h];
        float e = fdec(g_mxbits[layer * 3 + h]) + adn[h];
        m[h] = (e > 0.f) ? e : 0.2f * e;
    }

    float2 acc[H];
    float ssum[H];
#pragma unroll
    for (int h = 0; h < H; h++) { acc[h].x = 0.f; acc[h].y = 0.f; ssum[h] = 0.f; }

    for (int base = start; base < end; base += 32) {
        int nb = min(32, end - base);
        int src_l = 0;
        float w_l[H];
#pragma unroll
        for (int h = 0; h < H; h++) w_l[h] = 0.f;
        if (base + lane < end) {
            src_l = g_csr[base + lane];
#pragma unroll
            for (int h = 0; h < H; h++) {
                float e = g_as[src_l * H + h] + adn[h];
                e = (e > 0.f) ? e : 0.2f * e;
                float w = __expf(e - m[h]);
                w_l[h] = w;
                ssum[h] += w;
            }
        }
        for (int j = 0; j < nb; j++) {
            int src = __shfl_sync(0xffffffffu, src_l, j);
            const float2* hr = reinterpret_cast<const float2*>(hpre + (size_t)src * (H * 64));
#pragma unroll
            for (int h = 0; h < H; h++) {
                float w = __shfl_sync(0xffffffffu, w_l[h], j);
                float2 v = hr[h * 32 + lane];
                acc[h].x += w * v.x;
                acc[h].y += w * v.y;
            }
        }
    }

#pragma unroll
    for (int o = 16; o >= 1; o >>= 1)
#pragma unroll
        for (int h = 0; h < H; h++)
            ssum[h] += __shfl_xor_sync(0xffffffffu, ssum[h], o);

    float2* orow = reinterpret_cast<float2*>(out + (size_t)warp * (H * 64));
#pragma unroll
    for (int h = 0; h < H; h++) {
        float inv = 1.f / (ssum[h] + 1e-16f);
        int c = h * 64 + 2 * lane;
        float vx = acc[h].x * inv;
        float vy = acc[h].y * inv;
        if (mode == 0) {
            vx += bias[c];
            vy += bias[c + 1];
            vx = (vx - bnm[c]) * (bng[c] * rsqrtf(bnv[c] + 1e-5f)) + bnb[c];
            vy = (vy - bnm[c + 1]) * (bng[c + 1] * rsqrtf(bnv[c + 1] + 1e-5f)) + bnb[c + 1];
            vx = (vx > 0.f) ? vx : expm1f(vx);
            vy = (vy > 0.f) ? vy : expm1f(vy);
        }
        float2 o2; o2.x = vx; o2.y = vy;
        orow[h * 32 + lane] = o2;
    }
}

// ---------------- head: logits = u @ W2[64,8] + b, then log_softmax ----------------
__global__ void head_kernel(const float* __restrict__ u, const float* __restrict__ W,
                            const float* __restrict__ b, float* __restrict__ out, int Nn)
{
    int gtid = blockIdx.x * blockDim.x + threadIdx.x;
    int lane = threadIdx.x & 31;
    int warpg = gtid >> 5;
    int sub = lane >> 3, cls = lane & 7;
    int node = warpg * 4 + sub;
    float acc = 0.f;
    if (node < Nn) {
        const float* ur = u + (size_t)node * 64;
#pragma unroll 8
        for (int k = 0; k < 64; k++) acc += ur[k] * W[k * 8 + cls];
        acc += b[cls];
    }
    float mx = acc;
#pragma unroll
    for (int o = 4; o >= 1; o >>= 1) mx = fmaxf(mx, __shfl_xor_sync(0xffffffffu, mx, o));
    float se = expf(acc - mx);
#pragma unroll
    for (int o = 4; o >= 1; o >>= 1) se += __shfl_xor_sync(0xffffffffu, se, o);
    if (node < Nn) out[(size_t)node * 8 + cls] = acc - mx - logf(se);
}

// ---------------- host orchestration ----------------
extern "C" void kernel_launch(void* const* d_in, const int* in_sizes, int n_in,
                              void* d_out, int out_size)
{
    const float* x     = (const float*)d_in[0];
    const void*  ei    = d_in[1];
    const float* W1    = (const float*)d_in[2];
    const float* asr1  = (const float*)d_in[3];
    const float* adt1  = (const float*)d_in[4];
    const float* b1    = (const float*)d_in[5];
    const float* bn1g  = (const float*)d_in[6];
    const float* bn1b  = (const float*)d_in[7];
    const float* bn1m  = (const float*)d_in[8];
    const float* bn1v  = (const float*)d_in[9];
    const float* W2    = (const float*)d_in[10];
    const float* asr2  = (const float*)d_in[11];
    const float* adt2  = (const float*)d_in[12];
    const float* b2    = (const float*)d_in[13];
    const float* bn2g  = (const float*)d_in[14];
    const float* bn2b  = (const float*)d_in[15];
    const float* bn2m  = (const float*)d_in[16];
    const float* bn2v  = (const float*)d_in[17];
    const float* W3    = (const float*)d_in[18];
    const float* asr3  = (const float*)d_in[19];
    const float* adt3  = (const float*)d_in[20];
    const float* b3    = (const float*)d_in[21];
    const float* skipW = (const float*)d_in[22];
    const float* skipb = (const float*)d_in[23];
    const float* l1W   = (const float*)d_in[24];
    const float* l1b   = (const float*)d_in[25];
    const float* l2W   = (const float*)d_in[26];
    const float* l2b   = (const float*)d_in[27];

    int Nn = in_sizes[0] / 64;
    int E  = in_sizes[1] / 2;
    if (Nn > MAXN) Nn = MAXN;
    if (E > MAXE) E = MAXE;

    float *bufA, *bufB;
    cudaGetSymbolAddress((void**)&bufA, g_bufA);
    cudaGetSymbolAddress((void**)&bufB, g_bufB);

    int eb = (E + 255) / 256;
    int nb = (Nn + 1 + 255) / 256;
    int sb = (Nn + 1023) / 1024;      // scan blocks (<= 49)
    int gb = (Nn + 63) / 64;
    int ab = (Nn + 7) / 8;            // 8 warps per block

    // launches 1-3: dtype + zero + conv/deg
    detect_kernel<<<1, 256>>>((const unsigned int*)ei, E);
    zero_kernel<<<nb, 256>>>(Nn);
    conv_deg_kernel<<<eb, 256>>>(ei, E, Nn);

    // launch 4 (profiled slot): layer-1 GEMM — independent of CSR build
    gemm_kernel<192, 3><<<gb, 256>>>(x, W1, bufA, Nn, 64, 0, nullptr, nullptr, nullptr, asr1, adt1, 0);

    // CSR build
    scan_blocks<<<sb, 1024>>>(Nn);
    scan_tops<<<1, 64>>>(sb);
    scan_add<<<sb, 1024>>>(Nn);
    scat_kernel<<<eb, 256>>>(E);

    // --- layer 1 ---
    agg_kernel<3><<<ab, 256>>>(bufA, b1, bn1g, bn1b, bn1m, bn1v, bufB, Nn, 0, 0);

    // --- layer 2: 192 -> 2x64 ---
    gemm_kernel<128, 2><<<gb, 256>>>(bufB, W2, bufA, Nn, 192, 0, nullptr, nullptr, nullptr, asr2, adt2, 1);
    agg_kernel<2><<<ab, 256>>>(bufA, b2, bn2g, bn2b, bn2m, bn2v, bufB, Nn, 0, 1);

    // --- layer 3: 128 -> 64 (raw aggregation; b3 folded into skip epilogue) ---
    gemm_kernel<64, 1><<<gb, 256>>>(bufB, W3, bufA, Nn, 128, 0, nullptr, nullptr, nullptr, asr3, adt3, 2);
    agg_kernel<1><<<ab, 256>>>(bufA, nullptr, nullptr, nullptr, nullptr, nullptr, bufB, Nn, 1, 2);

    // --- skip: t = x@skipW + skip_b + b3 + agg3 ---
    gemm_kernel<64, 0><<<gb, 256>>>(x, skipW, bufA, Nn, 64, 1, skipb, b3, bufB, nullptr, nullptr, 0);
    // --- lin1: u = elu(t@l1W + l1b) ---
    gemm_kernel<64, 0><<<gb, 256>>>(bufA, l1W, bufB, Nn, 64, 2, l1b, nullptr, nullptr, nullptr, nullptr, 0);
    // --- lin2 + log_softmax ---
    head_kernel<<<(Nn * 8 + 255) / 256, 256>>>(bufB, l2W, l2b, (float*)d_out, Nn);
}